// round 10
// baseline (speedup 1.0000x reference)
#include <cuda_runtime.h>
#include <cuda_bf16.h>

// Problem constants
#define BB 64      // batch
#define NN 512     // tokens
#define EE 512     // embed dim
#define DD 1024    // 2E
#define TT 64      // decode steps

typedef unsigned long long ull;

// ---------------- device scratch ----------------
__device__ float g_enc[(size_t)BB * EE * NN];   // [b][e][n]  64 MB, L2-resident
__device__ float g_dec_t[DD * BB];              // decoder input, TRANSPOSED [k][b]
__device__ float g_hx_t[EE * BB];               // hx transposed [e(=k')][b]
__device__ float g_qpart[4][BB][EE];            // q partials [ks][b][e]
__device__ float g_scores[BB * NN];
__device__ float g_wsum;                        // sum of wr

// ---------------- packed fp32x2 helpers (sm_103a FFMA2) ----------------
__device__ __forceinline__ ull pack2(float x, float y) {
    ull r; asm("mov.b64 %0, {%1,%2};" : "=l"(r) : "f"(x), "f"(y)); return r;
}
__device__ __forceinline__ void unpack2(ull v, float& x, float& y) {
    asm("mov.b64 {%0,%1}, %2;" : "=f"(x), "=f"(y) : "l"(v));
}
__device__ __forceinline__ void ffma2(ull& d, ull a, ull b) {
    asm("fma.rn.f32x2 %0, %1, %2, %0;" : "+l"(d) : "l"(a), "l"(b));
}
__device__ __forceinline__ float ex2a(float x) {
    float r; asm("ex2.approx.f32 %0, %1;" : "=f"(r) : "f"(x)); return r;
}
__device__ __forceinline__ float rcpa(float x) {
    float r; asm("rcp.approx.f32 %0, %1;" : "=f"(r) : "f"(x)); return r;
}

#define C2L 2.885390081777926f   // 2*log2(e)

// =====================================================================
// K1: enc[b][e][n] = be[e] + sum_d te[b][n][d] * We[e][d]
// v2: 128x128 tile, 128 threads, 8e x 16n micro-tile.
// Per kk: 6 LDS.128 feed 64 FFMA2 (crossbar 192 vs fma 256 cyc/SM) -> fma-bound.
// Same k-accumulation order as v1 => bit-identical outputs.
// grid (4, 4, 64), block 128
// =====================================================================
__global__ __launch_bounds__(128) void enc_kernel(
    const float* __restrict__ te, const float* __restrict__ We,
    const float* __restrict__ be)
{
    const int b  = blockIdx.z;
    const int n0 = blockIdx.x * 128;
    const int e0 = blockIdx.y * 128;

    __shared__ __align__(16) float As[16][132];   // [k][e_local]
    __shared__ __align__(16) float Bs[16][132];   // [k][n_local]

    const int tid = threadIdx.x;       // 0..127
    const int ty  = tid >> 3;          // 0..15 -> e micro-row group (8 e's)
    const int tx  = tid & 7;           // 0..7  -> n micro-col group (16 n's)

    ull acc[8][8];
#pragma unroll
    for (int i = 0; i < 8; i++)
#pragma unroll
        for (int j = 0; j < 8; j++) acc[i][j] = 0ULL;

    const float* Aptr = We + (size_t)(e0 + tid) * DD;
    const float* Bptr = te + ((size_t)b * NN + (n0 + tid)) * DD;

    for (int k0 = 0; k0 < DD; k0 += 16) {
        // stage: each thread owns one e-row of A and one n-row of B (16 k's)
#pragma unroll
        for (int j = 0; j < 4; j++) {
            float4 a = *(const float4*)(Aptr + k0 + 4 * j);
            float4 c = *(const float4*)(Bptr + k0 + 4 * j);
            As[4 * j + 0][tid] = a.x; As[4 * j + 1][tid] = a.y;
            As[4 * j + 2][tid] = a.z; As[4 * j + 3][tid] = a.w;
            Bs[4 * j + 0][tid] = c.x; Bs[4 * j + 1][tid] = c.y;
            Bs[4 * j + 2][tid] = c.z; Bs[4 * j + 3][tid] = c.w;
        }
        __syncthreads();

#pragma unroll
        for (int kk = 0; kk < 16; kk++) {
            float4 av0 = *(const float4*)&As[kk][ty * 8];
            float4 av1 = *(const float4*)&As[kk][ty * 8 + 4];
            const ull* bp = (const ull*)&Bs[kk][tx * 16];   // 8 packed n-pairs
            ull b0 = bp[0], b1 = bp[1], b2 = bp[2], b3 = bp[3];
            ull b4 = bp[4], b5 = bp[5], b6 = bp[6], b7 = bp[7];
            float av[8] = {av0.x, av0.y, av0.z, av0.w, av1.x, av1.y, av1.z, av1.w};
#pragma unroll
            for (int i = 0; i < 8; i++) {
                ull ad = pack2(av[i], av[i]);
                ffma2(acc[i][0], ad, b0); ffma2(acc[i][1], ad, b1);
                ffma2(acc[i][2], ad, b2); ffma2(acc[i][3], ad, b3);
                ffma2(acc[i][4], ad, b4); ffma2(acc[i][5], ad, b5);
                ffma2(acc[i][6], ad, b6); ffma2(acc[i][7], ad, b7);
            }
        }
        __syncthreads();
    }

#pragma unroll
    for (int i = 0; i < 8; i++) {
        const int e = e0 + ty * 8 + i;
        const float bias = __ldg(&be[e]);
        float* orow = g_enc + ((size_t)b * EE + e) * NN + n0 + tx * 16;
#pragma unroll
        for (int jj = 0; jj < 4; jj++) {
            float x0, y0, x1, y1;
            unpack2(acc[i][2 * jj], x0, y0);
            unpack2(acc[i][2 * jj + 1], x1, y1);
            float4 v = make_float4(x0 + bias, y0 + bias, x1 + bias, y1 + bias);
            *(float4*)(orow + 4 * jj) = v;
        }
    }
}

// =====================================================================
// K0: g_dec_t[k][b] <- encoded_document[b][k]; block 0 also reduces wr.
// grid 64, block 256
// =====================================================================
__global__ __launch_bounds__(256) void init_kernel(
    const float* __restrict__ encdoc, const float* __restrict__ wr)
{
    const int b = blockIdx.x, t = threadIdx.x;
#pragma unroll
    for (int i = 0; i < 4; i++) {
        const int k = i * 256 + t;
        g_dec_t[k * BB + b] = encdoc[(size_t)b * DD + k];
    }
    if (b == 0) {
        __shared__ float red[256];
        red[t] = __ldg(&wr[t]) + __ldg(&wr[t + 256]);
        __syncthreads();
#pragma unroll
        for (int o = 128; o > 0; o >>= 1) {
            if (t < o) red[t] += red[t + o];
            __syncthreads();
        }
        if (t == 0) g_wsum = red[0];
    }
}

// =====================================================================
// K2: gates GEMM (full k, internal 4-way k-split reduced in smem) +
// fused LSTM activation. grid 128, block 256.
// Block owns 4 e rows x 3 gates x all 64 b. Same k-order as R3 =>
// bit-identical gates. (Proven correct in R7.)
// =====================================================================
__global__ __launch_bounds__(256) void gatesact_kernel(
    const float* __restrict__ W_ih, const float* __restrict__ b_ih,
    const float* __restrict__ b_hh)
{
    __shared__ __align__(16) float  s_x[4 * 32 * 64];    // 32KB [ks][kk][b]; reused as red
    __shared__ __align__(16) float2 s_w2[12 * 4 * 32];   // 12KB [r][ks][kk] (w,w) pairs

    const int bid = blockIdx.x, t = threadIdx.x;
    const int e0 = bid * 4;
    const int ks = t >> 6, el = (t >> 4) & 3, bq = t & 15;

    ull acc[3][2];
#pragma unroll
    for (int g = 0; g < 3; g++) { acc[g][0] = 0ULL; acc[g][1] = 0ULL; }

    for (int c = 0; c < 8; c++) {
        // stage x: 2048 float4 = [ks][kk][b]
#pragma unroll
        for (int i = 0; i < 8; i++) {
            const int i4 = i * 256 + t;
            const int b4 = i4 & 15, kk = (i4 >> 4) & 31, kss = i4 >> 9;
            float4 v = __ldg((const float4*)&g_dec_t[(kss * 256 + c * 32 + kk) * BB + b4 * 4]);
            *(float4*)&s_x[(kss * 32 + kk) * 64 + b4 * 4] = v;
        }
        // stage w (duplicated pairs): 1536 floats
#pragma unroll
        for (int j = 0; j < 6; j++) {
            const int idx = j * 256 + t;
            const int kk = idx & 31, kss = (idx >> 5) & 3, r = idx >> 7;  // r<12
            const int e = e0 + r / 3;
            const int gi = r % 3;
            const int grow = (gi == 0 ? 0 : (gi == 1 ? 2 * EE : 3 * EE)) + e;
            const float w = __ldg(&W_ih[(size_t)grow * DD + kss * 256 + c * 32 + kk]);
            s_w2[(r * 4 + kss) * 32 + kk] = make_float2(w, w);
        }
        __syncthreads();

#pragma unroll
        for (int kk = 0; kk < 32; kk++) {
            const float* xp = &s_x[(ks * 32 + kk) * 64 + bq * 4];
            ull a0 = *(const ull*)xp;
            ull a1 = *(const ull*)(xp + 2);
#pragma unroll
            for (int g = 0; g < 3; g++) {
                ull wp = *(const ull*)&s_w2[((el * 3 + g) * 4 + ks) * 32 + kk];
                ffma2(acc[g][0], wp, a0);
                ffma2(acc[g][1], wp, a1);
            }
        }
        __syncthreads();
    }

    // write partials into s_x (reused as red[ks][g][el][b])
#pragma unroll
    for (int g = 0; g < 3; g++) {
        float a, b2, c2, d2;
        unpack2(acc[g][0], a, b2);
        unpack2(acc[g][1], c2, d2);
        *(float4*)&s_x[(((ks * 3 + g) * 4 + el) * 64) + bq * 4] = make_float4(a, b2, c2, d2);
    }
    __syncthreads();

    // reduce 4 k-partials (fixed order) + biases + activation; coalesced tail
    {
        const int el2 = t >> 6, b = t & 63;
        const int e = e0 + el2;
        float gi = __ldg(&b_ih[e])          + __ldg(&b_hh[e]);
        float gg = __ldg(&b_ih[2 * EE + e]) + __ldg(&b_hh[2 * EE + e]);
        float go = __ldg(&b_ih[3 * EE + e]) + __ldg(&b_hh[3 * EE + e]);
#pragma unroll
        for (int kq = 0; kq < 4; kq++) {
            gi += s_x[((kq * 3 + 0) * 4 + el2) * 64 + b];
            gg += s_x[((kq * 3 + 1) * 4 + el2) * 64 + b];
            go += s_x[((kq * 3 + 2) * 4 + el2) * 64 + b];
        }
        const float c  = (1.f / (1.f + expf(-gi))) * tanhf(gg);
        g_hx_t[e * BB + b] = (1.f / (1.f + expf(-go))) * tanhf(c);
    }
}

// =====================================================================
// K3: q partials. grid 128 = 32 e-blocks x 4 k-splits, block 256.
// (unchanged from R3)
// =====================================================================
__global__ __launch_bounds__(256) void q_gemm_kernel(const float* __restrict__ Wd)
{
    const int eb = blockIdx.x & 31, ks = blockIdx.x >> 5;
    const int e0 = eb * 16, kbase = ks * 128;

    __shared__ __align__(16) float xs[32][64];
    __shared__ float ws[16][32];

    const int t = threadIdx.x, ec = t >> 4, bq = t & 15;
    ull acc0 = 0ULL, acc1 = 0ULL;

    for (int c = 0; c < 4; c++) {
        const int kc = kbase + c * 32;
#pragma unroll
        for (int i = 0; i < 8; i++) {
            const int idx = i * 256 + t;
            const int b = idx & 63, kk = idx >> 6;
            xs[kk][b] = g_hx_t[(kc + kk) * BB + b];
        }
#pragma unroll
        for (int j = 0; j < 2; j++) {
            const int idx = j * 256 + t;
            const int kk = idx & 31, ee = idx >> 5;
            ws[ee][kk] = __ldg(&Wd[(size_t)(e0 + ee) * EE + kc + kk]);
        }
        __syncthreads();

#pragma unroll
        for (int kk = 0; kk < 32; kk++) {
            float4 xv = *(const float4*)&xs[kk][bq * 4];
            const float w = ws[ec][kk];
            ull wp = pack2(w, w);
            ffma2(acc0, wp, pack2(xv.x, xv.y));
            ffma2(acc1, wp, pack2(xv.z, xv.w));
        }
        __syncthreads();
    }

    float a, b2, c2, d2;
    unpack2(acc0, a, b2);
    unpack2(acc1, c2, d2);
    const int b0 = bq * 4, e = e0 + ec;
    g_qpart[ks][b0 + 0][e] = a;
    g_qpart[ks][b0 + 1][e] = b2;
    g_qpart[ks][b0 + 2][e] = c2;
    g_qpart[ks][b0 + 3][e] = d2;
}

// =====================================================================
// K4: scores[b][n] = wsum - 2*sum_e wr_e * rcp(exp2(C2L*(enc+q)) + 1) + br
// grid (8, 64), block 256. (unchanged from R3)
// =====================================================================
__global__ __launch_bounds__(256) void attn_kernel(
    const float* __restrict__ wr, const float* __restrict__ bd,
    const float* __restrict__ br)
{
    __shared__ float qc[EE];
    __shared__ float wsm[EE];
    __shared__ float part[4][64];

    const int b  = blockIdx.y;
    const int t  = threadIdx.x;
    const int nl = t & 63;
    const int qr = t >> 6;
    const int n  = blockIdx.x * 64 + nl;

#pragma unroll
    for (int j = 0; j < 2; j++) {
        const int e = j * 256 + t;
        const float q = __ldg(&bd[e]) + g_qpart[0][b][e] + g_qpart[1][b][e]
                        + g_qpart[2][b][e] + g_qpart[3][b][e];
        qc[e]  = C2L * q;
        wsm[e] = __ldg(&wr[e]);
    }
    __syncthreads();

    const float* p = g_enc + ((size_t)b * EE + qr * 128) * NN + n;
    float acc = 0.f;
#pragma unroll 8
    for (int e = 0; e < 128; e++) {
        const float v  = __ldg(p + (size_t)e * NN);
        const int   eg = (qr << 7) + e;
        const float a  = fmaf(C2L, v, qc[eg]);
        const float tt = ex2a(a);
        const float u  = rcpa(tt + 1.f);
        acc = fmaf(wsm[eg], u, acc);
    }
    part[qr][nl] = acc;
    __syncthreads();

    if (t < 64) {
        const float s = g_wsum
                      - 2.f * (part[0][t] + part[1][t] + part[2][t] + part[3][t])
                      + __ldg(br);
        g_scores[b * NN + blockIdx.x * 64 + t] = s;
    }
}

// =====================================================================
// K5: per-b log_softmax + argmax (first-index ties) + transposed gather.
// grid 64, block 512. (unchanged from R3)
// =====================================================================
__global__ __launch_bounds__(512) void softmax_kernel(
    const float* __restrict__ te, float* __restrict__ out,
    int t_step, int write_idx)
{
    __shared__ float wm[16];
    __shared__ int   wi[16];
    __shared__ float wsum_[16];
    __shared__ float s_m;
    __shared__ int   s_i;
    __shared__ float s_lse;

    const int b = blockIdx.x, n = threadIdx.x;
    const int lane = n & 31, w = n >> 5;

    const float s = g_scores[b * NN + n];

    float m = s; int mi = n;
#pragma unroll
    for (int o = 16; o; o >>= 1) {
        const float om = __shfl_xor_sync(0xffffffffu, m, o);
        const int   oi = __shfl_xor_sync(0xffffffffu, mi, o);
        if (om > m || (om == m && oi < mi)) { m = om; mi = oi; }
    }
    if (lane == 0) { wm[w] = m; wi[w] = mi; }
    __syncthreads();
    if (w == 0) {
        float m2 = (lane < 16) ? wm[lane] : -3.4e38f;
        int   i2 = (lane < 16) ? wi[lane] : 0;
#pragma unroll
        for (int o = 8; o; o >>= 1) {
            const float om = __shfl_xor_sync(0xffffffffu, m2, o);
            const int   oi = __shfl_xor_sync(0xffffffffu, i2, o);
            if (om > m2 || (om == m2 && oi < i2)) { m2 = om; i2 = oi; }
        }
        if (lane == 0) { s_m = m2; s_i = i2; }
    }
    __syncthreads();
    const float mm  = s_m;
    const int   idx = s_i;

    float sum = expf(s - mm);
#pragma unroll
    for (int o = 16; o; o >>= 1) sum += __shfl_xor_sync(0xffffffffu, sum, o);
    if (lane == 0) wsum_[w] = sum;
    __syncthreads();
    if (w == 0) {
        float s2 = (lane < 16) ? wsum_[lane] : 0.f;
#pragma unroll
        for (int o = 8; o; o >>= 1) s2 += __shfl_xor_sync(0xffffffffu, s2, o);
        if (lane == 0) s_lse = mm + logf(s2);
    }
    __syncthreads();

    out[((size_t)b * TT + t_step) * NN + n] = s - s_lse;

    // gather next decoder input -> transposed g_dec_t[k][b]
    const float* src = te + ((size_t)b * NN + idx) * DD;
    g_dec_t[n * BB + b]          = src[n];
    g_dec_t[(n + 512) * BB + b]  = src[n + 512];

    if (write_idx && n == 0)
        out[(size_t)BB * TT * NN + b * TT + t_step] = (float)idx;
}

// =====================================================================
extern "C" void kernel_launch(void* const* d_in, const int* in_sizes, int n_in,
                              void* d_out, int out_size)
{
    const float* te     = (const float*)d_in[0];   // [64,512,1024]
    const float* encdoc = (const float*)d_in[1];   // [64,1024]
    const float* W_ih   = (const float*)d_in[2];   // [2048,1024]
    const float* b_ih   = (const float*)d_in[3];   // [2048]
    const float* b_hh   = (const float*)d_in[4];   // [2048]
    const float* Wd     = (const float*)d_in[5];   // [512,512]
    const float* bd     = (const float*)d_in[6];   // [512]
    const float* We     = (const float*)d_in[7];   // [512,1024]
    const float* be     = (const float*)d_in[8];   // [512]
    const float* wr     = (const float*)d_in[9];   // [1,512]
    const float* br     = (const float*)d_in[10];  // [1]

    float* out = (float*)d_out;
    const int write_idx = (out_size >= BB * TT * NN + BB * TT) ? 1 : 0;

    // Phase 1: loop-invariant encoder projection, stored [b][e][n]
    enc_kernel<<<dim3(NN / 128, EE / 128, BB), 128>>>(te, We, be);

    // Step-0 decoder input (transposed) + wr sum
    init_kernel<<<BB, 256>>>(encdoc, wr);

    // Sequential pointer decode: 4 kernels per step
    for (int t = 0; t < TT; t++) {
        gatesact_kernel<<<128, 256>>>(W_ih, b_ih, b_hh);
        q_gemm_kernel<<<128, 256>>>(Wd);
        attn_kernel<<<dim3(NN / 64, BB), 256>>>(wr, bd, br);
        softmax_kernel<<<BB, 512>>>(te, out, t, write_idx);
    }
}

// round 11
// speedup vs baseline: 1.2587x; 1.2587x over previous
#include <cuda_runtime.h>
#include <cuda_bf16.h>

// Problem constants
#define BB 64      // batch
#define NN 512     // tokens
#define EE 512     // embed dim
#define DD 1024    // 2E
#define TT 64      // decode steps

typedef unsigned long long ull;

// ---------------- device scratch ----------------
__device__ float g_enc[(size_t)BB * EE * NN];   // [b][e][n]  64 MB, L2-resident
__device__ float g_dec_t[DD * BB];              // decoder input, TRANSPOSED [k][b]
__device__ float g_hx_t[EE * BB];               // hx transposed [e(=k')][b]
__device__ float g_qpart[4][BB][EE];            // q partials [ks][b][e]
__device__ float g_scores[BB * NN];
__device__ float g_wsum;                        // sum of wr

// ---------------- packed fp32x2 helpers (sm_103a FFMA2) ----------------
__device__ __forceinline__ ull pack2(float x, float y) {
    ull r; asm("mov.b64 %0, {%1,%2};" : "=l"(r) : "f"(x), "f"(y)); return r;
}
__device__ __forceinline__ void unpack2(ull v, float& x, float& y) {
    asm("mov.b64 {%0,%1}, %2;" : "=f"(x), "=f"(y) : "l"(v));
}
__device__ __forceinline__ void ffma2(ull& d, ull a, ull b) {
    asm("fma.rn.f32x2 %0, %1, %2, %0;" : "+l"(d) : "l"(a), "l"(b));
}
__device__ __forceinline__ float ex2a(float x) {
    float r; asm("ex2.approx.f32 %0, %1;" : "=f"(r) : "f"(x)); return r;
}
__device__ __forceinline__ float rcpa(float x) {
    float r; asm("rcp.approx.f32 %0, %1;" : "=f"(r) : "f"(x)); return r;
}

#define C2L 2.885390081777926f   // 2*log2(e)

// =====================================================================
// K1: enc[b][e][n] = be[e] + sum_d te[b][n][d] * We[e][d]
// v1 EXACT (measured 753us, near FFMA2 roofline). grid (4,4,64), block 256
// =====================================================================
__global__ __launch_bounds__(256) void enc_kernel(
    const float* __restrict__ te, const float* __restrict__ We,
    const float* __restrict__ be)
{
    const int b  = blockIdx.z;
    const int n0 = blockIdx.x * 128;
    const int e0 = blockIdx.y * 128;

    __shared__ __align__(16) float As[16][132];
    __shared__ __align__(16) float Bs[16][132];

    const int tid = threadIdx.x;
    const int ty  = tid >> 4;
    const int tx  = tid & 15;

    ull acc[8][4];
#pragma unroll
    for (int i = 0; i < 8; i++)
#pragma unroll
        for (int j = 0; j < 4; j++) acc[i][j] = 0ULL;

    const int lrow = tid >> 2;
    const int lk4  = (tid & 3) * 4;
    const float* Aptr = We + (size_t)(e0 + lrow) * DD + lk4;
    const float* Bptr = te + ((size_t)b * NN + (n0 + lrow)) * DD + lk4;

    for (int k0 = 0; k0 < DD; k0 += 16) {
        float4 a0 = *(const float4*)(Aptr + k0);
        float4 a1 = *(const float4*)(Aptr + k0 + (size_t)64 * DD);
        float4 c0 = *(const float4*)(Bptr + k0);
        float4 c1 = *(const float4*)(Bptr + k0 + (size_t)64 * DD);
        As[lk4 + 0][lrow]      = a0.x; As[lk4 + 1][lrow]      = a0.y;
        As[lk4 + 2][lrow]      = a0.z; As[lk4 + 3][lrow]      = a0.w;
        As[lk4 + 0][lrow + 64] = a1.x; As[lk4 + 1][lrow + 64] = a1.y;
        As[lk4 + 2][lrow + 64] = a1.z; As[lk4 + 3][lrow + 64] = a1.w;
        Bs[lk4 + 0][lrow]      = c0.x; Bs[lk4 + 1][lrow]      = c0.y;
        Bs[lk4 + 2][lrow]      = c0.z; Bs[lk4 + 3][lrow]      = c0.w;
        Bs[lk4 + 0][lrow + 64] = c1.x; Bs[lk4 + 1][lrow + 64] = c1.y;
        Bs[lk4 + 2][lrow + 64] = c1.z; Bs[lk4 + 3][lrow + 64] = c1.w;
        __syncthreads();

#pragma unroll
        for (int kk = 0; kk < 16; kk++) {
            float4 av0 = *(const float4*)&As[kk][ty * 8];
            float4 av1 = *(const float4*)&As[kk][ty * 8 + 4];
            float4 bv0 = *(const float4*)&Bs[kk][tx * 8];
            float4 bv1 = *(const float4*)&Bs[kk][tx * 8 + 4];
            ull bp0 = pack2(bv0.x, bv0.y);
            ull bp1 = pack2(bv0.z, bv0.w);
            ull bp2 = pack2(bv1.x, bv1.y);
            ull bp3 = pack2(bv1.z, bv1.w);
            float av[8] = {av0.x, av0.y, av0.z, av0.w, av1.x, av1.y, av1.z, av1.w};
#pragma unroll
            for (int i = 0; i < 8; i++) {
                ull ad = pack2(av[i], av[i]);
                ffma2(acc[i][0], ad, bp0);
                ffma2(acc[i][1], ad, bp1);
                ffma2(acc[i][2], ad, bp2);
                ffma2(acc[i][3], ad, bp3);
            }
        }
        __syncthreads();
    }

#pragma unroll
    for (int i = 0; i < 8; i++) {
        const int e = e0 + ty * 8 + i;
        const float bias = __ldg(&be[e]);
        float* orow = g_enc + ((size_t)b * EE + e) * NN + n0 + tx * 8;
#pragma unroll
        for (int j = 0; j < 4; j++) {
            float x, y;
            unpack2(acc[i][j], x, y);
            float2 v = make_float2(x + bias, y + bias);
            *(float2*)(orow + 2 * j) = v;
        }
    }
}

// =====================================================================
// K0: g_dec_t[k][b] <- encoded_document[b][k]; block 0 also reduces wr.
// grid 64, block 256
// =====================================================================
__global__ __launch_bounds__(256) void init_kernel(
    const float* __restrict__ encdoc, const float* __restrict__ wr)
{
    const int b = blockIdx.x, t = threadIdx.x;
#pragma unroll
    for (int i = 0; i < 4; i++) {
        const int k = i * 256 + t;
        g_dec_t[k * BB + b] = encdoc[(size_t)b * DD + k];
    }
    if (b == 0) {
        __shared__ float red[256];
        red[t] = __ldg(&wr[t]) + __ldg(&wr[t + 256]);
        __syncthreads();
#pragma unroll
        for (int o = 128; o > 0; o >>= 1) {
            if (t < o) red[t] += red[t + o];
            __syncthreads();
        }
        if (t == 0) g_wsum = red[0];
    }
}

// =====================================================================
// K2: gates GEMM (full k, internal 4-way k-split reduced in smem) +
// fused LSTM activation. grid 128, block 256.
// Same k-order as R3 => bit-identical gates.
// =====================================================================
__global__ __launch_bounds__(256) void gatesact_kernel(
    const float* __restrict__ W_ih, const float* __restrict__ b_ih,
    const float* __restrict__ b_hh)
{
    __shared__ __align__(16) float  s_x[4 * 32 * 64];    // 32KB [ks][kk][b]; reused as red
    __shared__ __align__(16) float2 s_w2[12 * 4 * 32];   // 12KB [r][ks][kk] (w,w) pairs

    const int bid = blockIdx.x, t = threadIdx.x;
    const int e0 = bid * 4;
    const int ks = t >> 6, el = (t >> 4) & 3, bq = t & 15;

    ull acc[3][2];
#pragma unroll
    for (int g = 0; g < 3; g++) { acc[g][0] = 0ULL; acc[g][1] = 0ULL; }

    for (int c = 0; c < 8; c++) {
        // stage x: 2048 float4 = [ks][kk][b]
#pragma unroll
        for (int i = 0; i < 8; i++) {
            const int i4 = i * 256 + t;
            const int b4 = i4 & 15, kk = (i4 >> 4) & 31, kss = i4 >> 9;
            float4 v = __ldg((const float4*)&g_dec_t[(kss * 256 + c * 32 + kk) * BB + b4 * 4]);
            *(float4*)&s_x[(kss * 32 + kk) * 64 + b4 * 4] = v;
        }
        // stage w (duplicated pairs): 1536 floats
#pragma unroll
        for (int j = 0; j < 6; j++) {
            const int idx = j * 256 + t;
            const int kk = idx & 31, kss = (idx >> 5) & 3, r = idx >> 7;  // r<12
            const int e = e0 + r / 3;
            const int gi = r % 3;
            const int grow = (gi == 0 ? 0 : (gi == 1 ? 2 * EE : 3 * EE)) + e;
            const float w = __ldg(&W_ih[(size_t)grow * DD + kss * 256 + c * 32 + kk]);
            s_w2[(r * 4 + kss) * 32 + kk] = make_float2(w, w);
        }
        __syncthreads();

#pragma unroll
        for (int kk = 0; kk < 32; kk++) {
            const float* xp = &s_x[(ks * 32 + kk) * 64 + bq * 4];
            ull a0 = *(const ull*)xp;
            ull a1 = *(const ull*)(xp + 2);
#pragma unroll
            for (int g = 0; g < 3; g++) {
                ull wp = *(const ull*)&s_w2[((el * 3 + g) * 4 + ks) * 32 + kk];
                ffma2(acc[g][0], wp, a0);
                ffma2(acc[g][1], wp, a1);
            }
        }
        __syncthreads();
    }

    // write partials into s_x (reused as red[ks][g][el][b])
#pragma unroll
    for (int g = 0; g < 3; g++) {
        float a, b2, c2, d2;
        unpack2(acc[g][0], a, b2);
        unpack2(acc[g][1], c2, d2);
        *(float4*)&s_x[(((ks * 3 + g) * 4 + el) * 64) + bq * 4] = make_float4(a, b2, c2, d2);
    }
    __syncthreads();

    // reduce 4 k-partials (fixed order) + biases + activation; coalesced tail
    {
        const int el2 = t >> 6, b = t & 63;
        const int e = e0 + el2;
        float gi = __ldg(&b_ih[e])          + __ldg(&b_hh[e]);
        float gg = __ldg(&b_ih[2 * EE + e]) + __ldg(&b_hh[2 * EE + e]);
        float go = __ldg(&b_ih[3 * EE + e]) + __ldg(&b_hh[3 * EE + e]);
#pragma unroll
        for (int kq = 0; kq < 4; kq++) {
            gi += s_x[((kq * 3 + 0) * 4 + el2) * 64 + b];
            gg += s_x[((kq * 3 + 1) * 4 + el2) * 64 + b];
            go += s_x[((kq * 3 + 2) * 4 + el2) * 64 + b];
        }
        const float c  = (1.f / (1.f + expf(-gi))) * tanhf(gg);
        g_hx_t[e * BB + b] = (1.f / (1.f + expf(-go))) * tanhf(c);
    }
}

// =====================================================================
// K3: q partials, v2: SINGLE staging pass (xs 32KB + ws 8KB), one sync,
// then one 128-iteration FFMA2 loop. Same sequential k-order as R3 =>
// bit-identical qpart. grid 128 = 32 e-blocks x 4 k-splits, block 256.
// =====================================================================
__global__ __launch_bounds__(256) void q_gemm_kernel(const float* __restrict__ Wd)
{
    const int eb = blockIdx.x & 31, ks = blockIdx.x >> 5;
    const int e0 = eb * 16, kbase = ks * 128;

    __shared__ __align__(16) float xs[128][64];   // 32KB
    __shared__ __align__(16) float ws[16][128];   // 8KB

    const int t = threadIdx.x, ec = t >> 4, bq = t & 15;

    // stage xs: 2048 float4, max MLP
#pragma unroll
    for (int i = 0; i < 8; i++) {
        const int i4 = i * 256 + t;              // 0..2047
        const int kk = i4 >> 4, b4 = i4 & 15;
        *(float4*)&xs[kk][b4 * 4] =
            __ldg((const float4*)&g_hx_t[(kbase + kk) * BB + b4 * 4]);
    }
    // stage ws: 512 float4
#pragma unroll
    for (int i = 0; i < 2; i++) {
        const int i4 = i * 256 + t;              // 0..511
        const int ee = i4 >> 5, k4 = i4 & 31;
        *(float4*)&ws[ee][k4 * 4] =
            __ldg((const float4*)&Wd[(size_t)(e0 + ee) * EE + kbase + k4 * 4]);
    }
    __syncthreads();

    ull acc0 = 0ULL, acc1 = 0ULL;
#pragma unroll 16
    for (int kk = 0; kk < 128; kk++) {
        float4 xv = *(const float4*)&xs[kk][bq * 4];
        const float w = ws[ec][kk];
        ull wp = pack2(w, w);
        ffma2(acc0, wp, pack2(xv.x, xv.y));
        ffma2(acc1, wp, pack2(xv.z, xv.w));
    }

    float a, b2, c2, d2;
    unpack2(acc0, a, b2);
    unpack2(acc1, c2, d2);
    const int b0 = bq * 4, e = e0 + ec;
    g_qpart[ks][b0 + 0][e] = a;
    g_qpart[ks][b0 + 1][e] = b2;
    g_qpart[ks][b0 + 2][e] = c2;
    g_qpart[ks][b0 + 3][e] = d2;
}

// =====================================================================
// K4: scores[b][n] = wsum - 2*sum_e wr_e * rcp(exp2(C2L*(enc+q)) + 1) + br
// grid (8, 64), block 256. (exact R3)
// =====================================================================
__global__ __launch_bounds__(256) void attn_kernel(
    const float* __restrict__ wr, const float* __restrict__ bd,
    const float* __restrict__ br)
{
    __shared__ float qc[EE];
    __shared__ float wsm[EE];
    __shared__ float part[4][64];

    const int b  = blockIdx.y;
    const int t  = threadIdx.x;
    const int nl = t & 63;
    const int qr = t >> 6;
    const int n  = blockIdx.x * 64 + nl;

#pragma unroll
    for (int j = 0; j < 2; j++) {
        const int e = j * 256 + t;
        const float q = __ldg(&bd[e]) + g_qpart[0][b][e] + g_qpart[1][b][e]
                        + g_qpart[2][b][e] + g_qpart[3][b][e];
        qc[e]  = C2L * q;
        wsm[e] = __ldg(&wr[e]);
    }
    __syncthreads();

    const float* p = g_enc + ((size_t)b * EE + qr * 128) * NN + n;
    float acc = 0.f;
#pragma unroll 8
    for (int e = 0; e < 128; e++) {
        const float v  = __ldg(p + (size_t)e * NN);
        const int   eg = (qr << 7) + e;
        const float a  = fmaf(C2L, v, qc[eg]);
        const float tt = ex2a(a);
        const float u  = rcpa(tt + 1.f);
        acc = fmaf(wsm[eg], u, acc);
    }
    part[qr][nl] = acc;
    __syncthreads();

    if (t < 64) {
        const float s = g_wsum
                      - 2.f * (part[0][t] + part[1][t] + part[2][t] + part[3][t])
                      + __ldg(br);
        g_scores[b * NN + blockIdx.x * 64 + t] = s;
    }
}

// =====================================================================
// K5: per-b log_softmax + argmax (first-index ties) + transposed gather.
// grid 64, block 512. (exact R3)
// =====================================================================
__global__ __launch_bounds__(512) void softmax_kernel(
    const float* __restrict__ te, float* __restrict__ out,
    int t_step, int write_idx)
{
    __shared__ float wm[16];
    __shared__ int   wi[16];
    __shared__ float wsum_[16];
    __shared__ float s_m;
    __shared__ int   s_i;
    __shared__ float s_lse;

    const int b = blockIdx.x, n = threadIdx.x;
    const int lane = n & 31, w = n >> 5;

    const float s = g_scores[b * NN + n];

    float m = s; int mi = n;
#pragma unroll
    for (int o = 16; o; o >>= 1) {
        const float om = __shfl_xor_sync(0xffffffffu, m, o);
        const int   oi = __shfl_xor_sync(0xffffffffu, mi, o);
        if (om > m || (om == m && oi < mi)) { m = om; mi = oi; }
    }
    if (lane == 0) { wm[w] = m; wi[w] = mi; }
    __syncthreads();
    if (w == 0) {
        float m2 = (lane < 16) ? wm[lane] : -3.4e38f;
        int   i2 = (lane < 16) ? wi[lane] : 0;
#pragma unroll
        for (int o = 8; o; o >>= 1) {
            const float om = __shfl_xor_sync(0xffffffffu, m2, o);
            const int   oi = __shfl_xor_sync(0xffffffffu, i2, o);
            if (om > m2 || (om == m2 && oi < i2)) { m2 = om; i2 = oi; }
        }
        if (lane == 0) { s_m = m2; s_i = i2; }
    }
    __syncthreads();
    const float mm  = s_m;
    const int   idx = s_i;

    float sum = expf(s - mm);
#pragma unroll
    for (int o = 16; o; o >>= 1) sum += __shfl_xor_sync(0xffffffffu, sum, o);
    if (lane == 0) wsum_[w] = sum;
    __syncthreads();
    if (w == 0) {
        float s2 = (lane < 16) ? wsum_[lane] : 0.f;
#pragma unroll
        for (int o = 8; o; o >>= 1) s2 += __shfl_xor_sync(0xffffffffu, s2, o);
        if (lane == 0) s_lse = mm + logf(s2);
    }
    __syncthreads();

    out[((size_t)b * TT + t_step) * NN + n] = s - s_lse;

    // gather next decoder input -> transposed g_dec_t[k][b]
    const float* src = te + ((size_t)b * NN + idx) * DD;
    g_dec_t[n * BB + b]          = src[n];
    g_dec_t[(n + 512) * BB + b]  = src[n + 512];

    if (write_idx && n == 0)
        out[(size_t)BB * TT * NN + b * TT + t_step] = (float)idx;
}

// =====================================================================
extern "C" void kernel_launch(void* const* d_in, const int* in_sizes, int n_in,
                              void* d_out, int out_size)
{
    const float* te     = (const float*)d_in[0];   // [64,512,1024]
    const float* encdoc = (const float*)d_in[1];   // [64,1024]
    const float* W_ih   = (const float*)d_in[2];   // [2048,1024]
    const float* b_ih   = (const float*)d_in[3];   // [2048]
    const float* b_hh   = (const float*)d_in[4];   // [2048]
    const float* Wd     = (const float*)d_in[5];   // [512,512]
    const float* bd     = (const float*)d_in[6];   // [512]
    const float* We     = (const float*)d_in[7];   // [512,1024]
    const float* be     = (const float*)d_in[8];   // [512]
    const float* wr     = (const float*)d_in[9];   // [1,512]
    const float* br     = (const float*)d_in[10];  // [1]

    float* out = (float*)d_out;
    const int write_idx = (out_size >= BB * TT * NN + BB * TT) ? 1 : 0;

    // Phase 1: loop-invariant encoder projection, stored [b][e][n]
    enc_kernel<<<dim3(NN / 128, EE / 128, BB), 256>>>(te, We, be);

    // Step-0 decoder input (transposed) + wr sum
    init_kernel<<<BB, 256>>>(encdoc, wr);

    // Sequential pointer decode: 4 kernels per step
    for (int t = 0; t < TT; t++) {
        gatesact_kernel<<<128, 256>>>(W_ih, b_ih, b_hh);
        q_gemm_kernel<<<128, 256>>>(Wd);
        attn_kernel<<<dim3(NN / 64, BB), 256>>>(wr, bd, br);
        softmax_kernel<<<BB, 512>>>(te, out, t, write_idx);
    }
}